// round 9
// baseline (speedup 1.0000x reference)
#include <cuda_runtime.h>
#include <cstdint>

// DiagonalSISOCell: V=100000, D=64, N=16
// out[v,d,q] = sum_n ( exp(delta_v*A[d,n])*state[v,d,n] + delta_v*B[d,n]*x[v,d] ) * C[d,n,q]
// delta_v = softplus(x[v,:] @ w_delta + b_delta)

#define V_TOK 100000
#define VPAD  100224
#define LOG2E 1.4426950408889634f

__device__ float g_delta[VPAD];
__device__ float g_dxT[64 * VPAD];   // dxT[d][v] = delta_v * x[v,d]

// ---- per-warp smem layout (floats) ------------------------------------------
#define TILE_T 32                    // tokens per tile (J = 2 per lane)
#define P4     9                     // float4 pitch of a token row (36 floats)
#define W_T1   (TILE_T * 36)         // 1152 floats per tile buffer
#define W_C    (2 * 272)             // C padded per feature
#define W_AB   64
#define WSZ    (2 * W_T1 + W_C + W_AB)   // 2912 floats = 11648 B per warp

// ---------------------------------------------------------------------------
__device__ __forceinline__ float2 ffma2(float2 a, float2 b, float2 c) {
    float2 r;
    asm("fma.rn.f32x2 %0, %1, %2, %3;"
        : "=l"(*reinterpret_cast<unsigned long long*>(&r))
        : "l"(*reinterpret_cast<unsigned long long*>(&a)),
          "l"(*reinterpret_cast<unsigned long long*>(&b)),
          "l"(*reinterpret_cast<unsigned long long*>(&c)));
    return r;
}
__device__ __forceinline__ float ex2_approx(float x) {
    float r; asm("ex2.approx.f32 %0, %1;" : "=f"(r) : "f"(x)); return r;
}
__device__ __forceinline__ uint32_t smem_u32(const void* p) {
    uint32_t a;
    asm("{ .reg .u64 t; cvta.to.shared.u64 t, %1; cvt.u32.u64 %0, t; }"
        : "=r"(a) : "l"(p));
    return a;
}
__device__ __forceinline__ void cp16(uint32_t dst, const void* src) {
    asm volatile("cp.async.cg.shared.global [%0], [%1], 16;"
                 :: "r"(dst), "l"(src) : "memory");
}
__device__ __forceinline__ void cp_commit() {
    asm volatile("cp.async.commit_group;" ::: "memory");
}
__device__ __forceinline__ void cp_wait1() {
    asm volatile("cp.async.wait_group 1;" ::: "memory");
}

// ---------------------------------------------------------------------------
// Kernel 1: per 32-token block — delta[v] (softplus) and transposed
// dxT[d][v] = delta_v * x[v,d], coalesced reads AND writes.
// ---------------------------------------------------------------------------
__global__ void __launch_bounds__(128)
delta_kernel(const float* __restrict__ x,
             const float* __restrict__ w,
             const float* __restrict__ b)
{
    __shared__ float xs[32 * 65];
    __shared__ float ws[64];
    __shared__ float ds[32];

    const int tid = threadIdx.x;
    const int v0  = blockIdx.x * 32;

    if (tid < 64) ws[tid] = w[tid];

#pragma unroll
    for (int j = 0; j < 16; j++) {
        int idx = j * 128 + tid;
        int row = idx >> 6, col = idx & 63;
        xs[row * 65 + col] = x[(size_t)v0 * 64 + idx];
    }
    __syncthreads();

    {
        int t = tid >> 2, sub = tid & 3;
        float s = 0.f;
        const float* xr = xs + t * 65 + sub * 16;
        const float* wr = ws + sub * 16;
#pragma unroll
        for (int k = 0; k < 16; k++) s = fmaf(xr[k], wr[k], s);
        s += __shfl_xor_sync(0xffffffffu, s, 1);
        s += __shfl_xor_sync(0xffffffffu, s, 2);
        if (sub == 0) {
            float tt = s + b[0];
            ds[t] = fmaxf(tt, 0.0f) + log1pf(expf(-fabsf(tt)));
        }
    }
    __syncthreads();

    if (tid < 32) g_delta[v0 + tid] = ds[tid];

#pragma unroll
    for (int j = 0; j < 16; j++) {
        int d = j * 4 + (tid >> 5);
        int t = tid & 31;
        g_dxT[(size_t)d * VPAD + v0 + t] = ds[t] * xs[t * 65 + d];
    }
}

// ---------------------------------------------------------------------------
// Kernel 2: warp-independent d-PAIR tiles, double-buffered via cp.async.
// Warp owns features (2*dpair, 2*dpair+1) -> 128B/token rows, full sectors.
// 32-token tiles (2 per lane): buf(i) computed while buf(i+1) streams in.
// Lane = (fs=l>>4, q=l&15) owns tokens q, q+16. Only __syncwarp in hot loop.
// 4 blocks/SM (regs <= 128, smem 46.6KB/block) for latency hiding.
// ---------------------------------------------------------------------------
__global__ void __launch_bounds__(128, 4)
siso_kernel(const float* __restrict__ state,
            const float* __restrict__ log_nA,
            const float* __restrict__ Bm,
            const float* __restrict__ Cm,
            float* __restrict__ out,
            int chunk_sz)
{
    extern __shared__ float sm[];
    const int tid   = threadIdx.x;
    const int w     = tid >> 5;
    const int l     = tid & 31;
    const int grp   = blockIdx.x & 7;     // 8 dpair-groups of 4 warps
    const int chunk = blockIdx.x >> 3;
    const int dpair = grp * 4 + w;

    float*   W     = sm + w * WSZ;
    float4*  tile4 = reinterpret_cast<float4*>(W);          // [2][288] float4
    float*   Cws   = W + 2 * W_T1;
    float2*  ABws  = reinterpret_cast<float2*>(W + 2 * W_T1 + W_C);
    const uint32_t Wb = smem_u32(W);

    // --- per-warp init: C (padded 272/feature) + (A*log2e, B) ---------------
    {
        const float* src = Cm + dpair * 512;
#pragma unroll
        for (int k = 0; k < 16; k++) {
            int idx = k * 32 + l;
            Cws[(idx >> 8) * 272 + (idx & 255)] = src[idx];
        }
        int f = l >> 4, n = l & 15;
        int dd = dpair * 2 + f;
        float A2 = -__expf(log_nA[dd * 16 + n]) * LOG2E;
        ABws[l] = make_float2(A2, Bm[dd * 16 + n]);
    }

    const int fs = l >> 4;          // feature sub-index
    const int q  = l & 15;          // base token within 16-group
    const int f4 = l & 7;           // loader float4 index within 128B row
    const int tb = l >> 3;          // loader token sub-index (0..3)
    const int d  = dpair * 2 + fs;

    const float2* ABl = ABws + fs * 16;
    const float*  Cf  = Cws + fs * 272;
    const float*  dxr = g_dxT + (size_t)d * VPAD;

    const char* sg_b = reinterpret_cast<const char*>(state) + dpair * 128 + f4 * 16;
    float4*     og   = reinterpret_cast<float4*>(out) + dpair * 8 + f4;

    const int v_start = chunk * chunk_sz;
    if (v_start >= V_TOK) return;
    const int v_end   = min(V_TOK, v_start + chunk_sz);
    const int n_tiles = (v_end - v_start + TILE_T - 1) / TILE_T;

    // issue cp.async for tile ti into buffer b (8 x 16B per lane)
    auto issue = [&](int ti, int b) {
        if (ti < n_tiles) {
            const int v0 = v_start + ti * TILE_T;
            const int nt = min(TILE_T, v_end - v0);
            const uint32_t dst0 = Wb + (uint32_t)(b * W_T1 + f4 * 4) * 4;
            const char* src0 = sg_b + (size_t)v0 * 4096;
#pragma unroll
            for (int i = 0; i < 8; i++) {
                int t = 4 * i + tb;
                if (t < nt)
                    cp16(dst0 + (uint32_t)t * 144, src0 + (size_t)t * 4096);
            }
        }
        cp_commit();
    };

    issue(0, 0);
    issue(1, 1);

    for (int i = 0; i < n_tiles; i++) {
        const int b  = i & 1;
        const int v0 = v_start + i * TILE_T;
        const int nt = min(TILE_T, v_end - v0);
        const float4* tb4 = tile4 + b * (W_T1 / 4);
        float4*       tw4 = tile4 + b * (W_T1 / 4);

        // per-lane token scalars (issued before the wait for overlap)
        float dlt[2], dxv[2];
#pragma unroll
        for (int j = 0; j < 2; j++) {
            int t = q + 16 * j;
            bool vv = (t < nt);
            dlt[j] = vv ? __ldg(&g_delta[v0 + t]) : 0.f;
            dxv[j] = vv ? __ldg(&dxr[v0 + t])     : 0.f;
        }

        cp_wait1();      // tile i resident (tile i+1 may still be in flight)
        __syncwarp();

        // ---- compute: 2 tokens per lane ------------------------------------
        float2 acc[2][8];
#pragma unroll
        for (int j = 0; j < 2; j++)
#pragma unroll
            for (int p = 0; p < 8; p++) acc[j][p] = make_float2(0.f, 0.f);

        float4 s4[2];
#pragma unroll
        for (int n = 0; n < 16; n++) {
            if ((n & 3) == 0) {
#pragma unroll
                for (int j = 0; j < 2; j++)
                    s4[j] = tb4[(q + 16 * j) * P4 + fs * 4 + (n >> 2)];
            }
            const float2 ab = ABl[n];
            const float4* crow = reinterpret_cast<const float4*>(Cf + n * 16);
            float4 ca = crow[0], cb = crow[1], cc = crow[2], cd = crow[3];
            float2 c0 = make_float2(ca.x, ca.y), c1 = make_float2(ca.z, ca.w);
            float2 c2 = make_float2(cb.x, cb.y), c3 = make_float2(cb.z, cb.w);
            float2 c4 = make_float2(cc.x, cc.y), c5 = make_float2(cc.z, cc.w);
            float2 c6 = make_float2(cd.x, cd.y), c7 = make_float2(cd.z, cd.w);

#pragma unroll
            for (int j = 0; j < 2; j++) {
                float s = (n & 3) == 0 ? s4[j].x : (n & 3) == 1 ? s4[j].y
                        : (n & 3) == 2 ? s4[j].z : s4[j].w;
                float e  = ex2_approx(dlt[j] * ab.x);
                float nv = fmaf(e, s, dxv[j] * ab.y);
                float2 nv2 = make_float2(nv, nv);
                acc[j][0] = ffma2(nv2, c0, acc[j][0]);
                acc[j][1] = ffma2(nv2, c1, acc[j][1]);
                acc[j][2] = ffma2(nv2, c2, acc[j][2]);
                acc[j][3] = ffma2(nv2, c3, acc[j][3]);
                acc[j][4] = ffma2(nv2, c4, acc[j][4]);
                acc[j][5] = ffma2(nv2, c5, acc[j][5]);
                acc[j][6] = ffma2(nv2, c6, acc[j][6]);
                acc[j][7] = ffma2(nv2, c7, acc[j][7]);
            }
        }

        // ---- STS-out: each lane overwrites exactly the cells it read -------
#pragma unroll
        for (int j = 0; j < 2; j++)
#pragma unroll
            for (int p = 0; p < 4; p++)
                tw4[(q + 16 * j) * P4 + fs * 4 + p] =
                    make_float4(acc[j][2 * p].x,     acc[j][2 * p].y,
                                acc[j][2 * p + 1].x, acc[j][2 * p + 1].y);
        __syncwarp();

        // ---- LDS-out + STG: full sectors ------------------------------------
#pragma unroll
        for (int i2 = 0; i2 < 8; i2++) {
            int t = 4 * i2 + tb;
            float4 vo = tb4[t * P4 + f4];
            if (t < nt) og[(size_t)(v0 + t) * 256] = vo;
        }
        __syncwarp();   // buf b free

        issue(i + 2, b);  // refill this buffer
    }
}

// ---------------------------------------------------------------------------
// Launch
// ---------------------------------------------------------------------------
extern "C" void kernel_launch(void* const* d_in, const int* in_sizes, int n_in,
                              void* d_out, int out_size)
{
    const float* x       = (const float*)d_in[0];  // [V, D]
    const float* state   = (const float*)d_in[1];  // [V, D, N]
    const float* log_nA  = (const float*)d_in[2];  // [D, N]
    const float* B       = (const float*)d_in[3];  // [D, N]
    const float* C       = (const float*)d_in[4];  // [D, N, N]
    const float* w_delta = (const float*)d_in[5];  // [1, D]
    const float* b_delta = (const float*)d_in[6];  // [1]
    float* out = (float*)d_out;                    // [V, D, N]

    // Kernel 1: delta + transposed dx
    delta_kernel<<<V_TOK / 32, 128>>>(x, w_delta, b_delta);

    // Kernel 2: 8 dpair-groups x 74 chunks = 592 blocks (4/SM, 1 wave)
    const int n_chunks = 74;
    const int chunk_sz = 1376;                     // 43 tiles of 32
    const int smem_bytes = 4 * WSZ * 4;            // 46592 B per block

    cudaFuncSetAttribute(siso_kernel,
                         cudaFuncAttributeMaxDynamicSharedMemorySize, smem_bytes);
    siso_kernel<<<8 * n_chunks, 128, smem_bytes>>>(state, log_nA, B, C, out, chunk_sz);
}

// round 10
// speedup vs baseline: 1.0282x; 1.0282x over previous
#include <cuda_runtime.h>
#include <cstdint>

// DiagonalSISOCell: V=100000, D=64, N=16
// out[v,d,q] = sum_n ( exp(delta_v*A[d,n])*state[v,d,n] + delta_v*B[d,n]*x[v,d] ) * C[d,n,q]
// delta_v = softplus(x[v,:] @ w_delta + b_delta)

#define V_TOK 100000
#define LOG2E 1.4426950408889634f

__device__ float g_delta[V_TOK];

// ---- per-warp smem layout (floats) ------------------------------------------
#define TILE_T 32                    // tokens per tile (J = 2 per lane)
#define P4     9                     // float4 pitch of a token row (36 floats)
#define W_T1   (TILE_T * 36)         // 1152 floats per tile buffer
#define W_C    (2 * 272)             // C padded per feature
#define W_AB   64
#define WSZ    (2 * W_T1 + W_C + W_AB)   // 2912 floats = 11648 B per warp

// ---------------------------------------------------------------------------
__device__ __forceinline__ float2 ffma2(float2 a, float2 b, float2 c) {
    float2 r;
    asm("fma.rn.f32x2 %0, %1, %2, %3;"
        : "=l"(*reinterpret_cast<unsigned long long*>(&r))
        : "l"(*reinterpret_cast<unsigned long long*>(&a)),
          "l"(*reinterpret_cast<unsigned long long*>(&b)),
          "l"(*reinterpret_cast<unsigned long long*>(&c)));
    return r;
}
__device__ __forceinline__ float ex2_approx(float x) {
    float r; asm("ex2.approx.f32 %0, %1;" : "=f"(r) : "f"(x)); return r;
}
__device__ __forceinline__ uint32_t smem_u32(const void* p) {
    uint32_t a;
    asm("{ .reg .u64 t; cvta.to.shared.u64 t, %1; cvt.u32.u64 %0, t; }"
        : "=r"(a) : "l"(p));
    return a;
}
__device__ __forceinline__ void cp16(uint32_t dst, const void* src) {
    asm volatile("cp.async.cg.shared.global [%0], [%1], 16;"
                 :: "r"(dst), "l"(src) : "memory");
}
__device__ __forceinline__ void cp_commit() {
    asm volatile("cp.async.commit_group;" ::: "memory");
}
__device__ __forceinline__ void cp_wait1() {
    asm volatile("cp.async.wait_group 1;" ::: "memory");
}

// ---------------------------------------------------------------------------
// Kernel 1: delta[v] = softplus(dot(x[v,:], w) + b). 4 threads per token,
// float4 loads (full sectors), 2 shuffles, no smem, no syncthreads.
// ---------------------------------------------------------------------------
__global__ void __launch_bounds__(256)
delta_kernel(const float* __restrict__ x,
             const float* __restrict__ w,
             const float* __restrict__ b)
{
    const int tid = threadIdx.x;
    const int t   = blockIdx.x * 64 + (tid >> 2);
    const int sub = tid & 3;
    if (t >= V_TOK) return;

    const float4* xr = reinterpret_cast<const float4*>(x + (size_t)t * 64 + sub * 16);
    const float4* wr = reinterpret_cast<const float4*>(w + sub * 16);

    float s = 0.f;
#pragma unroll
    for (int i = 0; i < 4; i++) {
        float4 a = xr[i], ww = wr[i];
        s = fmaf(a.x, ww.x, s);
        s = fmaf(a.y, ww.y, s);
        s = fmaf(a.z, ww.z, s);
        s = fmaf(a.w, ww.w, s);
    }
    s += __shfl_xor_sync(0xffffffffu, s, 1);
    s += __shfl_xor_sync(0xffffffffu, s, 2);

    if (sub == 0) {
        float tt = s + b[0];
        g_delta[t] = fmaxf(tt, 0.0f) + log1pf(expf(-fabsf(tt)));
    }
}

// ---------------------------------------------------------------------------
// Kernel 2: warp-independent d-PAIR tiles, double-buffered via cp.async.
// Warp owns features (2*dpair, 2*dpair+1) -> 128B/token rows, full sectors.
// 32-token tiles (2 per lane). x is read DIRECTLY: lane (fs,q) loads
// x[v, 2dp+fs]; a 32B x-sector covers exactly this block's 8 features, so
// each sector is fetched once per block and L1-shared by its 4 warps.
// Only __syncwarp in the hot loop.
// ---------------------------------------------------------------------------
__global__ void __launch_bounds__(128, 4)
siso_kernel(const float* __restrict__ xg,
            const float* __restrict__ state,
            const float* __restrict__ log_nA,
            const float* __restrict__ Bm,
            const float* __restrict__ Cm,
            float* __restrict__ out,
            int chunk_sz)
{
    extern __shared__ float sm[];
    const int tid   = threadIdx.x;
    const int w     = tid >> 5;
    const int l     = tid & 31;
    const int grp   = blockIdx.x & 7;     // 8 dpair-groups of 4 warps
    const int chunk = blockIdx.x >> 3;
    const int dpair = grp * 4 + w;

    float*   W     = sm + w * WSZ;
    float4*  tile4 = reinterpret_cast<float4*>(W);          // [2][288] float4
    float*   Cws   = W + 2 * W_T1;
    float2*  ABws  = reinterpret_cast<float2*>(W + 2 * W_T1 + W_C);
    const uint32_t Wb = smem_u32(W);

    // --- per-warp init: C (padded 272/feature) + (A*log2e, B) ---------------
    {
        const float* src = Cm + dpair * 512;
#pragma unroll
        for (int k = 0; k < 16; k++) {
            int idx = k * 32 + l;
            Cws[(idx >> 8) * 272 + (idx & 255)] = src[idx];
        }
        int f = l >> 4, n = l & 15;
        int dd = dpair * 2 + f;
        float A2 = -__expf(log_nA[dd * 16 + n]) * LOG2E;
        ABws[l] = make_float2(A2, Bm[dd * 16 + n]);
    }

    const int fs = l >> 4;          // feature sub-index
    const int q  = l & 15;          // base token within 16-group
    const int f4 = l & 7;           // loader float4 index within 128B row
    const int tb = l >> 3;          // loader token sub-index (0..3)
    const int d  = dpair * 2 + fs;

    const float2* ABl = ABws + fs * 16;
    const float*  Cf  = Cws + fs * 272;

    const char* sg_b = reinterpret_cast<const char*>(state) + dpair * 128 + f4 * 16;
    float4*     og   = reinterpret_cast<float4*>(out) + dpair * 8 + f4;

    const int v_start = chunk * chunk_sz;
    if (v_start >= V_TOK) return;
    const int v_end   = min(V_TOK, v_start + chunk_sz);
    const int n_tiles = (v_end - v_start + TILE_T - 1) / TILE_T;

    // issue cp.async for tile ti into buffer b (8 x 16B per lane)
    auto issue = [&](int ti, int b) {
        if (ti < n_tiles) {
            const int v0 = v_start + ti * TILE_T;
            const int nt = min(TILE_T, v_end - v0);
            const uint32_t dst0 = Wb + (uint32_t)(b * W_T1 + f4 * 4) * 4;
            const char* src0 = sg_b + (size_t)v0 * 4096;
#pragma unroll
            for (int i = 0; i < 8; i++) {
                int t = 4 * i + tb;
                if (t < nt)
                    cp16(dst0 + (uint32_t)t * 144, src0 + (size_t)t * 4096);
            }
        }
        cp_commit();
    };

    issue(0, 0);
    issue(1, 1);

    for (int i = 0; i < n_tiles; i++) {
        const int b  = i & 1;
        const int v0 = v_start + i * TILE_T;
        const int nt = min(TILE_T, v_end - v0);
        const float4* tb4 = tile4 + b * (W_T1 / 4);
        float4*       tw4 = tile4 + b * (W_T1 / 4);

        // per-lane token scalars (issued before the wait for overlap)
        float dlt[2], dxv[2];
#pragma unroll
        for (int j = 0; j < 2; j++) {
            int t = q + 16 * j;
            bool vv = (t < nt);
            dlt[j]   = vv ? __ldg(&g_delta[v0 + t]) : 0.f;
            float xv = vv ? __ldg(&xg[(size_t)(v0 + t) * 64 + d]) : 0.f;
            dxv[j]   = dlt[j] * xv;
        }

        cp_wait1();      // tile i resident (tile i+1 may still be in flight)
        __syncwarp();

        // ---- compute: 2 tokens per lane ------------------------------------
        float2 acc[2][8];
#pragma unroll
        for (int j = 0; j < 2; j++)
#pragma unroll
            for (int p = 0; p < 8; p++) acc[j][p] = make_float2(0.f, 0.f);

        float4 s4[2];
#pragma unroll
        for (int n = 0; n < 16; n++) {
            if ((n & 3) == 0) {
#pragma unroll
                for (int j = 0; j < 2; j++)
                    s4[j] = tb4[(q + 16 * j) * P4 + fs * 4 + (n >> 2)];
            }
            const float2 ab = ABl[n];
            const float4* crow = reinterpret_cast<const float4*>(Cf + n * 16);
            float4 ca = crow[0], cb = crow[1], cc = crow[2], cd = crow[3];
            float2 c0 = make_float2(ca.x, ca.y), c1 = make_float2(ca.z, ca.w);
            float2 c2 = make_float2(cb.x, cb.y), c3 = make_float2(cb.z, cb.w);
            float2 c4 = make_float2(cc.x, cc.y), c5 = make_float2(cc.z, cc.w);
            float2 c6 = make_float2(cd.x, cd.y), c7 = make_float2(cd.z, cd.w);

#pragma unroll
            for (int j = 0; j < 2; j++) {
                float s = (n & 3) == 0 ? s4[j].x : (n & 3) == 1 ? s4[j].y
                        : (n & 3) == 2 ? s4[j].z : s4[j].w;
                float e  = ex2_approx(dlt[j] * ab.x);
                float nv = fmaf(e, s, dxv[j] * ab.y);
                float2 nv2 = make_float2(nv, nv);
                acc[j][0] = ffma2(nv2, c0, acc[j][0]);
                acc[j][1] = ffma2(nv2, c1, acc[j][1]);
                acc[j][2] = ffma2(nv2, c2, acc[j][2]);
                acc[j][3] = ffma2(nv2, c3, acc[j][3]);
                acc[j][4] = ffma2(nv2, c4, acc[j][4]);
                acc[j][5] = ffma2(nv2, c5, acc[j][5]);
                acc[j][6] = ffma2(nv2, c6, acc[j][6]);
                acc[j][7] = ffma2(nv2, c7, acc[j][7]);
            }
        }

        // ---- STS-out: each lane overwrites exactly the cells it read -------
#pragma unroll
        for (int j = 0; j < 2; j++)
#pragma unroll
            for (int p = 0; p < 4; p++)
                tw4[(q + 16 * j) * P4 + fs * 4 + p] =
                    make_float4(acc[j][2 * p].x,     acc[j][2 * p].y,
                                acc[j][2 * p + 1].x, acc[j][2 * p + 1].y);
        __syncwarp();

        // ---- LDS-out + STG: full sectors ------------------------------------
#pragma unroll
        for (int i2 = 0; i2 < 8; i2++) {
            int t = 4 * i2 + tb;
            float4 vo = tb4[t * P4 + f4];
            if (t < nt) og[(size_t)(v0 + t) * 256] = vo;
        }
        __syncwarp();   // buf b free

        issue(i + 2, b);  // refill this buffer
    }
}

// ---------------------------------------------------------------------------
// Launch
// ---------------------------------------------------------------------------
extern "C" void kernel_launch(void* const* d_in, const int* in_sizes, int n_in,
                              void* d_out, int out_size)
{
    const float* x       = (const float*)d_in[0];  // [V, D]
    const float* state   = (const float*)d_in[1];  // [V, D, N]
    const float* log_nA  = (const float*)d_in[2];  // [D, N]
    const float* B       = (const float*)d_in[3];  // [D, N]
    const float* C       = (const float*)d_in[4];  // [D, N, N]
    const float* w_delta = (const float*)d_in[5];  // [1, D]
    const float* b_delta = (const float*)d_in[6];  // [1]
    float* out = (float*)d_out;                    // [V, D, N]

    // Kernel 1: delta only (64 tokens per 256-thread block)
    delta_kernel<<<(V_TOK + 63) / 64, 256>>>(x, w_delta, b_delta);

    // Kernel 2: 8 dpair-groups x 74 chunks = 592 blocks (4/SM, 1 wave)
    const int n_chunks = 74;
    const int chunk_sz = 1376;                     // 43 tiles of 32
    const int smem_bytes = 4 * WSZ * 4;            // 46592 B per block

    cudaFuncSetAttribute(siso_kernel,
                         cudaFuncAttributeMaxDynamicSharedMemorySize, smem_bytes);
    siso_kernel<<<8 * n_chunks, 128, smem_bytes>>>(x, state, log_nA, B, C, out, chunk_sz);
}